// round 10
// baseline (speedup 1.0000x reference)
#include <cuda_runtime.h>

// DecorrelatedReNorm forward collapses algebraically:
//   W @ W_inv == I  =>  out = (X - running_mean) @ running_W
// Single fused kernel, 16384 blocks x 256 threads, 4 float4 per thread (exact
// cover). Blocks 0..63 additionally compute rmW = rm @ rW and zero-flags of
// E = running_W - I (last-block fold -> g_release). All other blocks FRONT-
// BATCH their X loads, then spin on g_release (wave-1 only; later waves see it
// set). E == 0 (actual buffers) -> pure stream out = X - rmW; else dense
// fallback. A g_done ticket resets all flags for the next graph replay.

#define CFEAT 512
#define TB    64
#define NBT   (CFEAT / TB)        // 8
#define PBLK  64                  // prep blocks (8 rows of rW each)
#define BLK   256
#define NV4   16777216LL          // out float4 count (131072 * 512 / 4)
#define AGRID 16384               // NV4 / (4 * BLK)

__device__ __align__(16) float g_partial[PBLK][CFEAT];
__device__ int                 g_flagpart[PBLK];
__device__ int                 g_flagmask[NBT];
__device__ int                 g_any;
__device__ __align__(16) float g_rmW[CFEAT];
__device__ int                 g_cnt;        // prep fold ticket (fold resets)
__device__ int                 g_release;    // set by fold, cleared by last block
__device__ int                 g_done;       // completion ticket (last resets)

__global__ void __launch_bounds__(BLK) fused_kernel(const float* __restrict__ X,
                                                    const float* __restrict__ rm,
                                                    const float* __restrict__ rW,
                                                    float* __restrict__ out) {
    const int b = blockIdx.x;
    const int t = threadIdx.x;
    const long long stride = (long long)AGRID * BLK;   // multiple of 128
    const long long i0     = (long long)b * BLK + t;

    const float4* X4 = reinterpret_cast<const float4*>(X);
    float4*       O4 = reinterpret_cast<float4*>(out);
    float4 x[4];

    if (b < PBLK) {
        // ---------------- prep: partials + flags, last block folds ----------
        int j4 = t & 127;            // float4 column 0..127
        int g  = t >> 7;             // row subgroup 0..1
        int c0 = b * 8 + g * 4;
        int j  = j4 * 4;
        int jb = j >> 6;

        __shared__ float4 sh[128];
        __shared__ int    shmask;
        __shared__ int    is_last;
        if (t == 0) shmask = 0;
        __syncthreads();

        const float4* W4 = reinterpret_cast<const float4*>(rW);
        float4 acc = make_float4(0.f, 0.f, 0.f, 0.f);
        int diff = 0;
        #pragma unroll
        for (int k = 0; k < 4; ++k) {
            int    c   = c0 + k;
            float4 w   = __ldg(&W4[c * (CFEAT / 4) + j4]);
            float  rmc = __ldg(&rm[c]);
            acc.x += rmc * w.x;  acc.y += rmc * w.y;
            acc.z += rmc * w.z;  acc.w += rmc * w.w;
            diff |= (w.x != ((c == j + 0) ? 1.0f : 0.0f));
            diff |= (w.y != ((c == j + 1) ? 1.0f : 0.0f));
            diff |= (w.z != ((c == j + 2) ? 1.0f : 0.0f));
            diff |= (w.w != ((c == j + 3) ? 1.0f : 0.0f));
        }
        if (g == 1) sh[j4] = acc;
        if (diff) atomicOr(&shmask, 1 << jb);   // bitwise: order-independent
        __syncthreads();
        if (g == 0) {
            float4 o = sh[j4];
            acc.x += o.x;  acc.y += o.y;  acc.z += o.z;  acc.w += o.w;
            reinterpret_cast<float4*>(g_partial[b])[j4] = acc;
        }
        if (t == 0) g_flagpart[b] = shmask;
        __threadfence();
        __syncthreads();
        if (t == 0) is_last = (atomicAdd(&g_cnt, 1) == PBLK - 1);
        __syncthreads();

        if (is_last) {               // block-uniform: whole block folds
            __threadfence();
            #pragma unroll
            for (int h = 0; h < 2; ++h) {
                int jj = t + h * BLK;
                float s = 0.0f;
                #pragma unroll 16
                for (int p = 0; p < PBLK; ++p) s += g_partial[p][jj];
                g_rmW[jj] = s;
            }
            if (t < NBT) {
                int m = 0;
                #pragma unroll
                for (int p = t * 8; p < t * 8 + 8; ++p) m |= g_flagpart[p];
                g_flagmask[t] = m;
            }
            int f = (t < PBLK) ? g_flagpart[t] : 0;
            int a = __syncthreads_or(f);
            if (t == 0) g_any = (a != 0);
            __syncthreads();
            __threadfence();
            if (t == 0) {
                g_cnt = 0;                            // fold ticket reset
                *(volatile int*)&g_release = 1;       // release everyone
            }
        }
        // prep blocks load their X share now (they lag ~3us; only 64 blocks)
        #pragma unroll
        for (int k = 0; k < 4; ++k) x[k] = __ldcs(&X4[i0 + k * stride]);
    } else {
        // ------------- apply blocks: front-batch X loads BEFORE the spin ----
        #pragma unroll
        for (int k = 0; k < 4; ++k) x[k] = __ldcs(&X4[i0 + k * stride]);
    }

    // ---- wait for prep results (wave-1 only; later waves pass through) ----
    if (t == 0) {
        while (*(volatile int*)&g_release == 0) __nanosleep(32);
    }
    __syncthreads();
    __threadfence();

    int any = g_any;   // uniform
    if (!any) {
        // stride % 128 == 0 -> thread's feature column fixed; rmW loaded once
        int    j4 = (int)(i0 & (CFEAT / 4 - 1));
        float4 r  = *reinterpret_cast<const float4*>(&g_rmW[j4 * 4]);
        #pragma unroll
        for (int k = 0; k < 4; ++k) {
            float4 o;
            o.x = x[k].x - r.x;  o.y = x[k].y - r.y;
            o.z = x[k].z - r.z;  o.w = x[k].w - r.w;
            __stcs(&O4[i0 + k * stride], o);
        }
    } else {
        // General fallback: out = X - rmW + X @ E over flagged 64-row blocks.
        #pragma unroll
        for (int k = 0; k < 4; ++k) {
            long long i  = i0 + k * stride;
            int       j4 = (int)(i & (CFEAT / 4 - 1));
            long long n  = i >> 7;
            int       j  = j4 * 4;
            int       jb = j / TB;

            float4 r = *reinterpret_cast<const float4*>(&g_rmW[j]);
            float4 o;
            o.x = x[k].x - r.x;  o.y = x[k].y - r.y;
            o.z = x[k].z - r.z;  o.w = x[k].w - r.w;

            const float* xrow = X + n * CFEAT;
            #pragma unroll
            for (int cb = 0; cb < NBT; ++cb) {
                if (!((__ldg(&g_flagmask[cb]) >> jb) & 1)) continue;
                #pragma unroll 4
                for (int ci = 0; ci < TB; ++ci) {
                    int   c  = cb * TB + ci;
                    float xc = xrow[c];
                    float4 w = *reinterpret_cast<const float4*>(&rW[c * CFEAT + j]);
                    o.x += xc * (w.x - ((c == j + 0) ? 1.0f : 0.0f));
                    o.y += xc * (w.y - ((c == j + 1) ? 1.0f : 0.0f));
                    o.z += xc * (w.z - ((c == j + 2) ? 1.0f : 0.0f));
                    o.w += xc * (w.w - ((c == j + 3) ? 1.0f : 0.0f));
                }
            }
            O4[i] = o;
        }
    }

    // ---- reset for the next graph replay: last block clears the flags ----
    __syncthreads();           // all stores + spin passage complete block-wide
    if (t == 0) {
        if (atomicAdd(&g_done, 1) == AGRID - 1) {   // everyone passed the spin
            g_done    = 0;
            *(volatile int*)&g_release = 0;
        }
    }
}

extern "C" void kernel_launch(void* const* d_in, const int* in_sizes, int n_in,
                              void* d_out, int out_size) {
    const float* X  = (const float*)d_in[0];  // [N, 512]
    const float* rm = (const float*)d_in[1];  // [512]
    const float* rW = (const float*)d_in[2];  // [512, 512]
    float* out = (float*)d_out;

    fused_kernel<<<AGRID, BLK>>>(X, rm, rW, out);
}